// round 10
// baseline (speedup 1.0000x reference)
#include <cuda_runtime.h>
#include <math_constants.h>

// Fixed shapes
#define B      32
#define C0     512
#define C1     1024
#define HW0    1444      // 38*38, divisible by 4
#define HW4_0  361       // HW0/4 in float4 units
#define HW1    361       // 19*19
#define THRESH 0.15f
#define NCH0   8         // channel chunks, level 0 (CPC = 64)
#define NCH1   16        // channel chunks, level 1 (CPC = 64)
#define CPC0   (C0/NCH0) // 64
#define CPC1   (C1/NCH1) // 64

// Output layout (float32): fw[2], embT0, embT1, embS0, embS1
#define OFF_FW  0
#define OFF_ET0 2
#define OFF_ET1 (OFF_ET0 + B*HW0)
#define OFF_ES0 (OFF_ET1 + B*HW1)
#define OFF_ES1 (OFF_ES0 + B*HW0)

// Static device scratch
__device__ float d_w0[B * C0];
__device__ float d_w1[B * C1];
__device__ float d_pc0[NCH0 * B * HW0];
__device__ float d_pt0[NCH0 * B * HW0];
__device__ float d_ps0[NCH0 * B * HW0];
__device__ float d_pc1[NCH1 * B * HW1];
__device__ float d_pt1[NCH1 * B * HW1];
__device__ float d_ps1[NCH1 * B * HW1];
__device__ float d_score[2 * B];
__device__ int   d_cnt = 0;

// ---------------------------------------------------------------------------
// Stage 1a: level-0 GradCAM weights. One warp = 2 rows, float4.
// ---------------------------------------------------------------------------
__global__ __launch_bounds__(256)
void k_gmean0(const float* __restrict__ g0, float* __restrict__ w0) {
    const int lane = threadIdx.x & 31;
    const int pair = blockIdx.x * 8 + (threadIdx.x >> 5);   // 0..8191
    const float4* p0 = reinterpret_cast<const float4*>(g0) + (size_t)(2 * pair) * HW4_0;
    const float4* p1 = p0 + HW4_0;
    float4 a0 = {0,0,0,0}, a1 = {0,0,0,0};
    #pragma unroll 4
    for (int i = lane; i < HW4_0; i += 32) {
        float4 v0 = __ldcs(p0 + i);
        float4 v1 = __ldcs(p1 + i);
        a0.x += v0.x; a0.y += v0.y; a0.z += v0.z; a0.w += v0.w;
        a1.x += v1.x; a1.y += v1.y; a1.z += v1.z; a1.w += v1.w;
    }
    float s0 = (a0.x + a0.y) + (a0.z + a0.w);
    float s1 = (a1.x + a1.y) + (a1.z + a1.w);
    #pragma unroll
    for (int o = 16; o; o >>= 1) {
        s0 += __shfl_xor_sync(0xffffffffu, s0, o);
        s1 += __shfl_xor_sync(0xffffffffu, s1, o);
    }
    if (lane == 0) {
        w0[2 * pair]     = s0 * (1.f / HW0);
        w0[2 * pair + 1] = s1 * (1.f / HW0);
    }
}

// ---------------------------------------------------------------------------
// Stage 1b: level-1 GradCAM weights. One warp = 4 rows, scalar interleaved.
// ---------------------------------------------------------------------------
__global__ __launch_bounds__(256)
void k_gmean1(const float* __restrict__ g1, float* __restrict__ w1) {
    const int lane = threadIdx.x & 31;
    const int quad = blockIdx.x * 8 + (threadIdx.x >> 5);   // 0..8191
    const float* p = g1 + (size_t)(4 * quad) * HW1;
    float s0 = 0.f, s1 = 0.f, s2 = 0.f, s3 = 0.f;
    #pragma unroll 4
    for (int i = lane; i < HW1; i += 32) {
        s0 += __ldcs(p + i);
        s1 += __ldcs(p + HW1 + i);
        s2 += __ldcs(p + 2 * HW1 + i);
        s3 += __ldcs(p + 3 * HW1 + i);
    }
    #pragma unroll
    for (int o = 16; o; o >>= 1) {
        s0 += __shfl_xor_sync(0xffffffffu, s0, o);
        s1 += __shfl_xor_sync(0xffffffffu, s1, o);
        s2 += __shfl_xor_sync(0xffffffffu, s2, o);
        s3 += __shfl_xor_sync(0xffffffffu, s3, o);
    }
    if (lane == 0) {
        const float inv = 1.f / HW1;
        w1[4 * quad]     = s0 * inv;
        w1[4 * quad + 1] = s1 * inv;
        w1[4 * quad + 2] = s2 * inv;
        w1[4 * quad + 3] = s3 * inv;
    }
}

// ---------------------------------------------------------------------------
// Stage 2a: level-0 cam partials (float4 along hw). grid (3, B, NCH0) x 128.
// ---------------------------------------------------------------------------
__global__ __launch_bounds__(128)
void k_cam0(const float* __restrict__ Tf0, const float* __restrict__ Sf0,
            const float* __restrict__ w0,
            float* __restrict__ pc0, float* __restrict__ pt0, float* __restrict__ ps0) {
    __shared__ float sw[CPC0];
    const int b = blockIdx.y, chunk = blockIdx.z, tid = threadIdx.x;
    if (tid < CPC0) sw[tid] = w0[b * C0 + chunk * CPC0 + tid];
    __syncthreads();

    const int q = blockIdx.x * 128 + tid;
    if (q >= HW4_0) return;
    const size_t rb = (size_t)(b * C0 + chunk * CPC0) * HW4_0 + q;
    const float4* tp = reinterpret_cast<const float4*>(Tf0) + rb;
    const float4* sp = reinterpret_cast<const float4*>(Sf0) + rb;

    float4 ac = {0,0,0,0}, at = {0,0,0,0}, as4 = {0,0,0,0};
    #pragma unroll 8
    for (int c = 0; c < CPC0; ++c) {
        float4 t = __ldcs(tp + (size_t)c * HW4_0);
        float4 s = __ldcs(sp + (size_t)c * HW4_0);
        float  wv = sw[c];
        ac.x = fmaf(wv, t.x, ac.x); ac.y = fmaf(wv, t.y, ac.y);
        ac.z = fmaf(wv, t.z, ac.z); ac.w = fmaf(wv, t.w, ac.w);
        at.x += t.x; at.y += t.y; at.z += t.z; at.w += t.w;
        as4.x += s.x; as4.y += s.y; as4.z += s.z; as4.w += s.w;
    }
    const size_t o = (size_t)(chunk * B + b) * HW4_0 + q;
    reinterpret_cast<float4*>(pc0)[o] = ac;
    reinterpret_cast<float4*>(pt0)[o] = at;
    reinterpret_cast<float4*>(ps0)[o] = as4;
}

// ---------------------------------------------------------------------------
// Stage 2b: level-1 cam partials (scalar along hw). grid (3, B, NCH1) x 128.
// ---------------------------------------------------------------------------
__global__ __launch_bounds__(128)
void k_cam1(const float* __restrict__ Tf1, const float* __restrict__ Sf1,
            const float* __restrict__ w1,
            float* __restrict__ pc1, float* __restrict__ pt1, float* __restrict__ ps1) {
    __shared__ float sw[CPC1];
    const int b = blockIdx.y, chunk = blockIdx.z, tid = threadIdx.x;
    if (tid < CPC1) sw[tid] = w1[b * C1 + chunk * CPC1 + tid];
    __syncthreads();

    const int hw = blockIdx.x * 128 + tid;
    if (hw >= HW1) return;
    const size_t rb = (size_t)(b * C1 + chunk * CPC1) * HW1 + hw;
    const float* tp = Tf1 + rb;
    const float* sp = Sf1 + rb;

    float ac = 0.f, at = 0.f, as_ = 0.f;
    #pragma unroll 8
    for (int c = 0; c < CPC1; ++c) {
        float t = __ldcs(tp + (size_t)c * HW1);
        float s = __ldcs(sp + (size_t)c * HW1);
        ac = fmaf(sw[c], t, ac);
        at += t;
        as_ += s;
    }
    const size_t o = (size_t)(chunk * B + b) * HW1 + hw;
    pc1[o] = ac; pt1[o] = at; ps1[o] = as_;
}

// ---------------------------------------------------------------------------
// Stage 3: per-level finish kernels (combine + stats + mask). Both share the
// global counter d_cnt; the 64th arriving block (across BOTH kernels, which
// may run concurrently on different streams) computes fw.
// ---------------------------------------------------------------------------
template <int C, int HW, int CHUNKS, int PPT>
__device__ __forceinline__
void finish_impl(const float* __restrict__ pc, const float* __restrict__ pt,
                 const float* __restrict__ ps,
                 float* __restrict__ outT, float* __restrict__ outS,
                 float* __restrict__ score_slot, int b,
                 float* smx, float* ssm, float* sthr) {
    constexpr float invC  = 1.f / (float)C;
    constexpr float invHW = 1.f / (float)HW;
    const int t = threadIdx.x;

    float camv[PPT], tv[PPT], sv[PPT];
    float mx = -CUDART_INF_F, sm = 0.f;

    #pragma unroll
    for (int p = 0; p < PPT; ++p) {
        const int i = p * 1024 + t;
        camv[p] = 0.f; tv[p] = 0.f; sv[p] = 0.f;
        if (i < HW) {
            float cc = 0.f, tt = 0.f, ss = 0.f;
            #pragma unroll
            for (int ch = 0; ch < CHUNKS; ++ch) {
                const size_t o = (size_t)(ch * B + b) * HW + i;
                cc += pc[o]; tt += pt[o]; ss += ps[o];
            }
            camv[p] = cc;
            tv[p]   = tt * invC;
            sv[p]   = ss * invC;
            mx = fmaxf(mx, cc);
            sm += fmaxf(cc, 0.f);
        }
    }

    smx[t] = mx; ssm[t] = sm;
    __syncthreads();
    #pragma unroll
    for (int s = 512; s; s >>= 1) {
        if (t < s) { smx[t] = fmaxf(smx[t], smx[t + s]); ssm[t] += ssm[t + s]; }
        __syncthreads();
    }
    if (t == 0) {
        *score_slot = ssm[0] * invHW;
        *sthr = fabsf(smx[0] * THRESH);
    }
    __syncthreads();
    const float thr = *sthr;

    #pragma unroll
    for (int p = 0; p < PPT; ++p) {
        const int i = p * 1024 + t;
        if (i < HW) {
            const bool m = camv[p] > thr;
            const size_t o = (size_t)b * HW + i;
            outT[o] = m ? tv[p] : 0.f;
            outS[o] = m ? sv[p] : 0.f;
        }
    }
}

__device__ __forceinline__
void fw_tail(float* __restrict__ out, float* __restrict__ score) {
    if (threadIdx.x == 0) {
        __threadfence();
        const int old = atomicAdd(&d_cnt, 1);
        if (old == 63) {
            __threadfence();
            float s0 = 0.f, s1 = 0.f;
            for (int i = 0; i < B; ++i) { s0 += score[i]; s1 += score[B + i]; }
            const float inv = 1.f / (s0 + s1);
            out[OFF_FW + 0] = s0 * inv;
            out[OFF_FW + 1] = s1 * inv;
            d_cnt = 0;   // reset for graph replay determinism
        }
    }
}

__global__ __launch_bounds__(1024)
void k_finish0(const float* __restrict__ pc0, const float* __restrict__ pt0,
               const float* __restrict__ ps0,
               float* __restrict__ out, float* __restrict__ score) {
    __shared__ float smx[1024], ssm[1024];
    __shared__ float sthr;
    const int b = blockIdx.x;
    finish_impl<C0, HW0, NCH0, 2>(pc0, pt0, ps0,
                                  out + OFF_ET0, out + OFF_ES0,
                                  score + b, b, smx, ssm, &sthr);
    fw_tail(out, score);
}

__global__ __launch_bounds__(1024)
void k_finish1(const float* __restrict__ pc1, const float* __restrict__ pt1,
               const float* __restrict__ ps1,
               float* __restrict__ out, float* __restrict__ score) {
    __shared__ float smx[1024], ssm[1024];
    __shared__ float sthr;
    const int b = blockIdx.x;
    finish_impl<C1, HW1, NCH1, 1>(pc1, pt1, ps1,
                                  out + OFF_ET1, out + OFF_ES1,
                                  score + B + b, b, smx, ssm, &sthr);
    fw_tail(out, score);
}

// ---------------------------------------------------------------------------
// Static stream/event objects (created at process init, BEFORE the harness's
// memory checkpoints; no device-memory allocation in kernel_launch itself).
// ---------------------------------------------------------------------------
namespace {
struct ForkCtx {
    cudaStream_t s2;
    cudaEvent_t  eFork, eJoin;
    ForkCtx() {
        cudaStreamCreateWithFlags(&s2, cudaStreamNonBlocking);
        cudaEventCreateWithFlags(&eFork, cudaEventDisableTiming);
        cudaEventCreateWithFlags(&eJoin, cudaEventDisableTiming);
    }
};
ForkCtx g_fork;   // static init
}

// ---------------------------------------------------------------------------
extern "C" void kernel_launch(void* const* d_in, const int* in_sizes, int n_in,
                              void* d_out, int out_size) {
    const float* Tf0 = (const float*)d_in[0];
    const float* Tf1 = (const float*)d_in[1];
    const float* Sf0 = (const float*)d_in[2];
    const float* Sf1 = (const float*)d_in[3];
    const float* g0  = (const float*)d_in[4];
    const float* g1  = (const float*)d_in[5];
    float* out = (float*)d_out;

    float *w0, *w1, *pc0, *pt0, *ps0, *pc1, *pt1, *ps1, *score;
    cudaGetSymbolAddress((void**)&w0,  d_w0);
    cudaGetSymbolAddress((void**)&w1,  d_w1);
    cudaGetSymbolAddress((void**)&pc0, d_pc0);
    cudaGetSymbolAddress((void**)&pt0, d_pt0);
    cudaGetSymbolAddress((void**)&ps0, d_ps0);
    cudaGetSymbolAddress((void**)&pc1, d_pc1);
    cudaGetSymbolAddress((void**)&pt1, d_pt1);
    cudaGetSymbolAddress((void**)&ps1, d_ps1);
    cudaGetSymbolAddress((void**)&score, d_score);

    // ---- fork: second stream joins the capture via event dependency ----
    cudaEventRecord(g_fork.eFork, 0);
    cudaStreamWaitEvent(g_fork.s2, g_fork.eFork, 0);

    // ---- chain 0 (default stream): level-0 pipeline ----
    k_gmean0<<<1024, 256>>>(g0, w0);
    {
        dim3 grid(3, B, NCH0);   // 768 blocks of 128
        k_cam0<<<grid, 128>>>(Tf0, Sf0, w0, pc0, pt0, ps0);
    }
    k_finish0<<<32, 1024>>>(pc0, pt0, ps0, out, score);

    // ---- chain 1 (stream s2): level-1 pipeline ----
    k_gmean1<<<1024, 256, 0, g_fork.s2>>>(g1, w1);
    {
        dim3 grid(3, B, NCH1);   // 1536 blocks of 128
        k_cam1<<<grid, 128, 0, g_fork.s2>>>(Tf1, Sf1, w1, pc1, pt1, ps1);
    }
    k_finish1<<<32, 1024, 0, g_fork.s2>>>(pc1, pt1, ps1, out, score);

    // ---- join ----
    cudaEventRecord(g_fork.eJoin, g_fork.s2);
    cudaStreamWaitEvent(0, g_fork.eJoin, 0);
}

// round 11
// speedup vs baseline: 1.0145x; 1.0145x over previous
#include <cuda_runtime.h>
#include <math_constants.h>

// Fixed shapes
#define B      32
#define C0     512
#define C1     1024
#define HW0    1444      // 38*38, divisible by 4
#define HW4_0  361       // HW0/4 in float4 units
#define HW1    361       // 19*19
#define THRESH 0.15f
#define NCH0   8         // channel chunks, level 0 (CPC = 64)
#define NCH1   16        // channel chunks, level 1 (CPC = 64)
#define CPC0   (C0/NCH0) // 64
#define CPC1   (C1/NCH1) // 64

// Output layout (float32): fw[2], embT0, embT1, embS0, embS1
#define OFF_FW  0
#define OFF_ET0 2
#define OFF_ET1 (OFF_ET0 + B*HW0)
#define OFF_ES0 (OFF_ET1 + B*HW1)
#define OFF_ES1 (OFF_ES0 + B*HW0)

// Static device scratch
__device__ float d_w0[B * C0];
__device__ float d_w1[B * C1];
__device__ float d_pc0[NCH0 * B * HW0];
__device__ float d_pt0[NCH0 * B * HW0];
__device__ float d_ps0[NCH0 * B * HW0];
__device__ float d_pc1[NCH1 * B * HW1];
__device__ float d_pt1[NCH1 * B * HW1];
__device__ float d_ps1[NCH1 * B * HW1];
__device__ float d_score[2 * B];
__device__ int   d_cnt = 0;

// ---------------------------------------------------------------------------
// Phase A (one launch, 6400 blocks x 128): gmean (g0+g1) AND Sf channel-sum
// partials, with block indices INTERLEAVED (period 25 = 16 gmean + 9 Sf) so
// every SM holds a mix of both access patterns for the whole launch.
// ---------------------------------------------------------------------------
__global__ __launch_bounds__(128)
void k_phaseA(const float* __restrict__ g0, const float* __restrict__ g1,
              const float* __restrict__ Sf0, const float* __restrict__ Sf1,
              float* __restrict__ w0, float* __restrict__ w1,
              float* __restrict__ ps0, float* __restrict__ ps1) {
    const int grp = blockIdx.x / 25;
    const int r   = blockIdx.x % 25;

    if (r < 16) {
        // ============ gmean segment (4096 virtual blocks) ============
        const int gblk = grp * 16 + r;          // 0..4095
        const int lane = threadIdx.x & 31;
        const int warp = threadIdx.x >> 5;      // 0..3

        if (gblk < 2048) {
            // level 0: one warp = 2 rows, float4. pairs 0..8191
            const int pair = gblk * 4 + warp;
            const float4* p0 = reinterpret_cast<const float4*>(g0) + (size_t)(2 * pair) * HW4_0;
            const float4* p1 = p0 + HW4_0;
            float4 a0 = {0,0,0,0}, a1 = {0,0,0,0};
            #pragma unroll 2
            for (int i = lane; i < HW4_0; i += 32) {
                float4 v0 = __ldcs(p0 + i);
                float4 v1 = __ldcs(p1 + i);
                a0.x += v0.x; a0.y += v0.y; a0.z += v0.z; a0.w += v0.w;
                a1.x += v1.x; a1.y += v1.y; a1.z += v1.z; a1.w += v1.w;
            }
            float s0 = (a0.x + a0.y) + (a0.z + a0.w);
            float s1 = (a1.x + a1.y) + (a1.z + a1.w);
            #pragma unroll
            for (int o = 16; o; o >>= 1) {
                s0 += __shfl_xor_sync(0xffffffffu, s0, o);
                s1 += __shfl_xor_sync(0xffffffffu, s1, o);
            }
            if (lane == 0) {
                w0[2 * pair]     = s0 * (1.f / HW0);
                w0[2 * pair + 1] = s1 * (1.f / HW0);
            }
        } else {
            // level 1: one warp = 4 rows, scalar interleaved. quads 0..8191
            const int quad = (gblk - 2048) * 4 + warp;
            const float* p = g1 + (size_t)(4 * quad) * HW1;
            float s0 = 0.f, s1 = 0.f, s2 = 0.f, s3 = 0.f;
            #pragma unroll 2
            for (int i = lane; i < HW1; i += 32) {
                s0 += __ldcs(p + i);
                s1 += __ldcs(p + HW1 + i);
                s2 += __ldcs(p + 2 * HW1 + i);
                s3 += __ldcs(p + 3 * HW1 + i);
            }
            #pragma unroll
            for (int o = 16; o; o >>= 1) {
                s0 += __shfl_xor_sync(0xffffffffu, s0, o);
                s1 += __shfl_xor_sync(0xffffffffu, s1, o);
                s2 += __shfl_xor_sync(0xffffffffu, s2, o);
                s3 += __shfl_xor_sync(0xffffffffu, s3, o);
            }
            if (lane == 0) {
                const float inv = 1.f / HW1;
                w1[4 * quad]     = s0 * inv;
                w1[4 * quad + 1] = s1 * inv;
                w1[4 * quad + 2] = s2 * inv;
                w1[4 * quad + 3] = s3 * inv;
            }
        }
    } else {
        // ============ Sf channel-sum segment (2304 virtual blocks) ============
        const int sblk = grp * 9 + (r - 16);    // 0..2303
        const int tid  = threadIdx.x;

        if (sblk < 768) {
            // level 0: float4 along hw. x=sblk%3, b=(sblk/3)%32, chunk=sblk/96
            const int x = sblk % 3, b = (sblk / 3) % 32, chunk = sblk / 96;
            const int q = x * 128 + tid;
            if (q >= HW4_0) return;
            const float4* sp = reinterpret_cast<const float4*>(Sf0)
                             + (size_t)(b * C0 + chunk * CPC0) * HW4_0 + q;
            float4 acc = {0,0,0,0};
            #pragma unroll 8
            for (int c = 0; c < CPC0; ++c) {
                float4 s = __ldcs(sp + (size_t)c * HW4_0);
                acc.x += s.x; acc.y += s.y; acc.z += s.z; acc.w += s.w;
            }
            reinterpret_cast<float4*>(ps0)[(size_t)(chunk * B + b) * HW4_0 + q] = acc;
        } else {
            // level 1: scalar along hw
            const int t = sblk - 768;           // 0..1535
            const int x = t % 3, b = (t / 3) % 32, chunk = t / 96;
            const int hw = x * 128 + tid;
            if (hw >= HW1) return;
            const float* sp = Sf1 + (size_t)(b * C1 + chunk * CPC1) * HW1 + hw;
            float acc = 0.f;
            #pragma unroll 8
            for (int c = 0; c < CPC1; ++c) acc += __ldcs(sp + (size_t)c * HW1);
            ps1[(size_t)(chunk * B + b) * HW1 + hw] = acc;
        }
    }
}

// ---------------------------------------------------------------------------
// Phase B: Tf-only pass -> pc (weighted) and pt (plain channel sums).
// grid (3, B, NCH0+NCH1) = 2304 blocks x 128.
// ---------------------------------------------------------------------------
__global__ __launch_bounds__(128)
void k_camT(const float* __restrict__ Tf0, const float* __restrict__ w0,
            float* __restrict__ pc0, float* __restrict__ pt0,
            const float* __restrict__ Tf1, const float* __restrict__ w1,
            float* __restrict__ pc1, float* __restrict__ pt1) {
    __shared__ float sw[64];
    const int b = blockIdx.y, z = blockIdx.z, tid = threadIdx.x;

    if (z < NCH0) {
        const int chunk = z;
        if (tid < CPC0) sw[tid] = w0[b * C0 + chunk * CPC0 + tid];
        __syncthreads();

        const int q = blockIdx.x * 128 + tid;
        if (q >= HW4_0) return;
        const float4* tp = reinterpret_cast<const float4*>(Tf0)
                         + (size_t)(b * C0 + chunk * CPC0) * HW4_0 + q;
        float4 ac = {0,0,0,0}, at = {0,0,0,0};
        #pragma unroll 8
        for (int c = 0; c < CPC0; ++c) {
            float4 t = __ldcs(tp + (size_t)c * HW4_0);
            const float wv = sw[c];
            ac.x = fmaf(wv, t.x, ac.x); ac.y = fmaf(wv, t.y, ac.y);
            ac.z = fmaf(wv, t.z, ac.z); ac.w = fmaf(wv, t.w, ac.w);
            at.x += t.x; at.y += t.y; at.z += t.z; at.w += t.w;
        }
        const size_t o = (size_t)(chunk * B + b) * HW4_0 + q;
        reinterpret_cast<float4*>(pc0)[o] = ac;
        reinterpret_cast<float4*>(pt0)[o] = at;
    } else {
        const int chunk = z - NCH0;
        if (tid < CPC1) sw[tid] = w1[b * C1 + chunk * CPC1 + tid];
        __syncthreads();

        const int hw = blockIdx.x * 128 + tid;
        if (hw >= HW1) return;
        const float* tp = Tf1 + (size_t)(b * C1 + chunk * CPC1) * HW1 + hw;
        float ac = 0.f, at = 0.f;
        #pragma unroll 8
        for (int c = 0; c < CPC1; ++c) {
            float t = __ldcs(tp + (size_t)c * HW1);
            ac = fmaf(sw[c], t, ac);
            at += t;
        }
        const size_t o = (size_t)(chunk * B + b) * HW1 + hw;
        pc1[o] = ac; pt1[o] = at;
    }
}

// ---------------------------------------------------------------------------
// Phase C: combine chunks + stats + mask + fw. 64 blocks x 1024 threads.
// ---------------------------------------------------------------------------
template <int C, int HW, int CHUNKS, int PPT>
__device__ __forceinline__
void finish_impl(const float* __restrict__ pc, const float* __restrict__ pt,
                 const float* __restrict__ ps,
                 float* __restrict__ outT, float* __restrict__ outS,
                 float* __restrict__ score_slot, int b,
                 float* smx, float* ssm, float* sthr) {
    constexpr float invC  = 1.f / (float)C;
    constexpr float invHW = 1.f / (float)HW;
    const int t = threadIdx.x;

    float camv[PPT], tv[PPT], sv[PPT];
    float mx = -CUDART_INF_F, sm = 0.f;

    #pragma unroll
    for (int p = 0; p < PPT; ++p) {
        const int i = p * 1024 + t;
        camv[p] = 0.f; tv[p] = 0.f; sv[p] = 0.f;
        if (i < HW) {
            float cc = 0.f, tt = 0.f, ss = 0.f;
            #pragma unroll
            for (int ch = 0; ch < CHUNKS; ++ch) {
                const size_t o = (size_t)(ch * B + b) * HW + i;
                cc += pc[o]; tt += pt[o]; ss += ps[o];
            }
            camv[p] = cc;
            tv[p]   = tt * invC;
            sv[p]   = ss * invC;
            mx = fmaxf(mx, cc);
            sm += fmaxf(cc, 0.f);
        }
    }

    smx[t] = mx; ssm[t] = sm;
    __syncthreads();
    #pragma unroll
    for (int s = 512; s; s >>= 1) {
        if (t < s) { smx[t] = fmaxf(smx[t], smx[t + s]); ssm[t] += ssm[t + s]; }
        __syncthreads();
    }
    if (t == 0) {
        *score_slot = ssm[0] * invHW;
        *sthr = fabsf(smx[0] * THRESH);
    }
    __syncthreads();
    const float thr = *sthr;

    #pragma unroll
    for (int p = 0; p < PPT; ++p) {
        const int i = p * 1024 + t;
        if (i < HW) {
            const bool m = camv[p] > thr;
            const size_t o = (size_t)b * HW + i;
            outT[o] = m ? tv[p] : 0.f;
            outS[o] = m ? sv[p] : 0.f;
        }
    }
}

__global__ __launch_bounds__(1024)
void k_finish_all(const float* __restrict__ pc0, const float* __restrict__ pt0,
                  const float* __restrict__ ps0,
                  const float* __restrict__ pc1, const float* __restrict__ pt1,
                  const float* __restrict__ ps1,
                  float* __restrict__ out, float* __restrict__ score) {
    __shared__ float smx[1024], ssm[1024];
    __shared__ float sthr;

    if (blockIdx.x < 32) {
        const int b = blockIdx.x;
        finish_impl<C0, HW0, NCH0, 2>(pc0, pt0, ps0,
                                      out + OFF_ET0, out + OFF_ES0,
                                      score + b, b, smx, ssm, &sthr);
    } else {
        const int b = blockIdx.x - 32;
        finish_impl<C1, HW1, NCH1, 1>(pc1, pt1, ps1,
                                      out + OFF_ET1, out + OFF_ES1,
                                      score + B + b, b, smx, ssm, &sthr);
    }

    if (threadIdx.x == 0) {
        __threadfence();
        const int old = atomicAdd(&d_cnt, 1);
        if (old == 63) {
            __threadfence();
            float s0 = 0.f, s1 = 0.f;
            for (int i = 0; i < B; ++i) { s0 += score[i]; s1 += score[B + i]; }
            const float inv = 1.f / (s0 + s1);
            out[OFF_FW + 0] = s0 * inv;
            out[OFF_FW + 1] = s1 * inv;
            d_cnt = 0;   // reset for graph replay determinism
        }
    }
}

// ---------------------------------------------------------------------------
extern "C" void kernel_launch(void* const* d_in, const int* in_sizes, int n_in,
                              void* d_out, int out_size) {
    const float* Tf0 = (const float*)d_in[0];
    const float* Tf1 = (const float*)d_in[1];
    const float* Sf0 = (const float*)d_in[2];
    const float* Sf1 = (const float*)d_in[3];
    const float* g0  = (const float*)d_in[4];
    const float* g1  = (const float*)d_in[5];
    float* out = (float*)d_out;

    float *w0, *w1, *pc0, *pt0, *ps0, *pc1, *pt1, *ps1, *score;
    cudaGetSymbolAddress((void**)&w0,  d_w0);
    cudaGetSymbolAddress((void**)&w1,  d_w1);
    cudaGetSymbolAddress((void**)&pc0, d_pc0);
    cudaGetSymbolAddress((void**)&pt0, d_pt0);
    cudaGetSymbolAddress((void**)&ps0, d_ps0);
    cudaGetSymbolAddress((void**)&pc1, d_pc1);
    cudaGetSymbolAddress((void**)&pt1, d_pt1);
    cudaGetSymbolAddress((void**)&ps1, d_ps1);
    cudaGetSymbolAddress((void**)&score, d_score);

    // Phase A: gmean + Sf sums, interleaved blocks (284 MB)
    k_phaseA<<<6400, 128>>>(g0, g1, Sf0, Sf1, w0, w1, ps0, ps1);

    // Phase B: Tf pass -> pc, pt (142 MB)
    {
        dim3 grid(3, B, NCH0 + NCH1);   // 2304 blocks of 128
        k_camT<<<grid, 128>>>(Tf0, w0, pc0, pt0, Tf1, w1, pc1, pt1);
    }

    // Phase C: combine + stats + mask + fw
    k_finish_all<<<64, 1024>>>(pc0, pt0, ps0, pc1, pt1, ps1, out, score);
}